// round 9
// baseline (speedup 1.0000x reference)
#include <cuda_runtime.h>
#include <cstdint>

// Sparse ConvTranspose3d on GB300 (sm_103a) — mma.sync tf32 tensor cores.
//   out[r,:] = bias + sum_{(k,n): out_index[k,n]==r} feats[n,:] @ weight[k,:,:]^T
//
// R9: scatter epilogue coalesced via SMEM staging. Each warp writes WHOLE
// output rows (32 lanes x 2 floats = 256B contiguous) -> L1 store wavefronts
// drop ~8x vs fragment-order scatter. D staged with XOR-chunk swizzle
// (STS <=2-way, LDS conflict-free). counts-split: count==1 -> st.global.cs.v2
// of acc+bias, else red.global.add.v2 onto conditionally bias-initialized rows.

#define CIN    64
#define COUT   64
#define TILE_N 128
#define KCHUNK 9
#define LDA    68          // padded row stride for A/W tiles (floats)
#define MAX_ROWS (60000 * 27)

__device__ int g_counts[MAX_ROWS];

// ---------------------------------------------------------------- pre-pass ----
__global__ void zero_counts_kernel(int n4) {
    int i = blockIdx.x * blockDim.x + threadIdx.x;
    if (i < n4) reinterpret_cast<int4*>(g_counts)[i] = make_int4(0, 0, 0, 0);
}
__global__ void count_kernel(const int* __restrict__ oi, int total) {
    int i = blockIdx.x * blockDim.x + threadIdx.x;
    if (i < total) atomicAdd(&g_counts[oi[i]], 1);
}
// init rows whose count != 1 (count==0: pure bias; count>=2: bias base for atomics)
__global__ void cond_bias_init_kernel(const float4* __restrict__ bias4,
                                      float4* __restrict__ out4, int n_out) {
    int r = blockIdx.x * blockDim.x + threadIdx.x;
    if (r < n_out && g_counts[r] != 1) {
        #pragma unroll
        for (int j = 0; j < 16; j++) out4[(size_t)r * 16 + j] = bias4[j];
    }
}

// ---------------------------------------------------------------- helpers ----
__device__ __forceinline__ uint32_t to_tf32(float f) {
    uint32_t u;
    asm("cvt.rna.tf32.f32 %0, %1;" : "=r"(u) : "f"(f));
    return u;
}
__device__ __forceinline__ uint32_t f2u(float f) { return __float_as_uint(f); }

__device__ __forceinline__ void mma_tf32(float c[4], const uint32_t a[4],
                                         uint32_t b0, uint32_t b1) {
    asm volatile(
        "mma.sync.aligned.m16n8k8.row.col.f32.tf32.tf32.f32 "
        "{%0,%1,%2,%3}, {%4,%5,%6,%7}, {%8,%9}, {%0,%1,%2,%3};"
        : "+f"(c[0]), "+f"(c[1]), "+f"(c[2]), "+f"(c[3])
        : "r"(a[0]), "r"(a[1]), "r"(a[2]), "r"(a[3]), "r"(b0), "r"(b1));
}

__device__ __forceinline__ void st_cs_v2(float* p, float x, float y) {
    asm volatile("st.global.cs.v2.f32 [%0], {%1, %2};"
                 :: "l"(p), "f"(x), "f"(y) : "memory");
}

// ------------------------------------------------------------- main kernel ----
// dyn smem (floats): As[128*68] | Wb[2*64*68] | Ds[128*64]
#define OFF_W  (TILE_N * LDA)
#define OFF_D  (OFF_W + 2 * COUT * LDA)
#define SMEM_F (OFF_D + TILE_N * COUT)

__global__ void __launch_bounds__(256, 2) spconvt_mma_kernel(
    const float* __restrict__ feats,     // [N, 64]
    const float* __restrict__ weight,    // [27, 64, 64]
    const float* __restrict__ bias,      // [64]
    const int*   __restrict__ out_index, // [27, N]
    float*       __restrict__ out,       // [n_out, 64]
    int N, int KV)
{
    extern __shared__ float smem[];
    float* As = smem;
    float* Wb = smem + OFF_W;
    float* Ds = smem + OFF_D;

    const int tid  = threadIdx.x;
    const int w    = tid >> 5;               // warp 0..7
    const int lane = tid & 31;
    const int g    = lane >> 2;              // group 0..7
    const int t    = lane & 3;               // thread-in-group 0..3
    const int n0   = blockIdx.x * TILE_N;
    const int k0   = blockIdx.y * KCHUNK;

    // ---- A tile: LDG -> cvt.rna.tf32 -> padded SMEM ----
    const float4* f4 = reinterpret_cast<const float4*>(feats);
    #pragma unroll
    for (int j = 0; j < 8; j++) {
        int idx = tid + 256 * j;              // 0..2047
        int p = idx >> 4, q = idx & 15;
        int n = n0 + p;
        float4 v = make_float4(0.f, 0.f, 0.f, 0.f);
        if (n < N) v = f4[(size_t)n * 16 + q];
        float* dst = As + p * LDA + q * 4;
        dst[0] = __uint_as_float(to_tf32(v.x));
        dst[1] = __uint_as_float(to_tf32(v.y));
        dst[2] = __uint_as_float(to_tf32(v.z));
        dst[3] = __uint_as_float(to_tf32(v.w));
    }
    // ---- W[k0] -> buf0 ----
    {
        const float4* ws = reinterpret_cast<const float4*>(weight + (size_t)k0 * COUT * CIN);
        #pragma unroll
        for (int j = 0; j < 4; j++) {
            int idx = tid + 256 * j;          // 0..1023
            int c = idx >> 4, q = idx & 15;
            float4 v = ws[idx];
            float* dst = Wb + c * LDA + q * 4;
            dst[0] = __uint_as_float(to_tf32(v.x));
            dst[1] = __uint_as_float(to_tf32(v.y));
            dst[2] = __uint_as_float(to_tf32(v.z));
            dst[3] = __uint_as_float(to_tf32(v.w));
        }
    }

    // per-lane bias pair for coalesced epilogue: cols 2*lane, 2*lane+1
    const float2 bl = __ldg(reinterpret_cast<const float2*>(bias) + lane);

    __syncthreads();

    const int pr = 16 * w + g;                // owned point rows: pr and pr+8
    int buf = 0;

    for (int kk = 0; kk < KCHUNK; kk++) {
        int k = k0 + kk;
        if (k >= KV) break;
        bool more = (kk + 1 < KCHUNK) && (k + 1 < KV);

        // prefetch W[k+1] into regs (latency hidden under MMA loop)
        float4 wreg[4];
        if (more) {
            const float4* ws = reinterpret_cast<const float4*>(
                weight + (size_t)(k + 1) * COUT * CIN);
            #pragma unroll
            for (int j = 0; j < 4; j++) wreg[j] = ws[tid + 256 * j];
        }

        const float* Wc = Wb + buf * (COUT * LDA);

        float acc[8][4];
        #pragma unroll
        for (int nt = 0; nt < 8; nt++)
            #pragma unroll
            for (int x = 0; x < 4; x++) acc[nt][x] = 0.f;

        #pragma unroll
        for (int kc = 0; kc < 8; kc++) {
            const int kb = kc * 8;
            uint32_t a[4];
            a[0] = f2u(As[(pr)     * LDA + kb + t]);
            a[1] = f2u(As[(pr + 8) * LDA + kb + t]);
            a[2] = f2u(As[(pr)     * LDA + kb + t + 4]);
            a[3] = f2u(As[(pr + 8) * LDA + kb + t + 4]);
            #pragma unroll
            for (int nt = 0; nt < 8; nt++) {
                int c = 8 * nt + g;
                uint32_t b0 = f2u(Wc[c * LDA + kb + t]);
                uint32_t b1 = f2u(Wc[c * LDA + kb + t + 4]);
                mma_tf32(acc[nt], a, b0, b1);
            }
        }

        // ---- stage D to SMEM, chunk-swizzled: phys chunk = nt ^ (row & 7) ----
        // rows pr, pr+8 share (row & 7) == g
        #pragma unroll
        for (int nt = 0; nt < 8; nt++) {
            int ch = nt ^ g;
            float2 v0 = make_float2(acc[nt][0], acc[nt][1]);
            float2 v1 = make_float2(acc[nt][2], acc[nt][3]);
            *reinterpret_cast<float2*>(Ds + (pr)     * COUT + ch * 8 + 2 * t) = v0;
            *reinterpret_cast<float2*>(Ds + (pr + 8) * COUT + ch * 8 + 2 * t) = v1;
        }
        __syncthreads();

        // ---- stage W[k+1] (overlaps the global-store epilogue below) ----
        if (more) {
            float* dstb = Wb + (buf ^ 1) * (COUT * LDA);
            #pragma unroll
            for (int j = 0; j < 4; j++) {
                int idx = tid + 256 * j;
                int c = idx >> 4, q = idx & 15;
                float* dst = dstb + c * LDA + q * 4;
                dst[0] = __uint_as_float(to_tf32(wreg[j].x));
                dst[1] = __uint_as_float(to_tf32(wreg[j].y));
                dst[2] = __uint_as_float(to_tf32(wreg[j].z));
                dst[3] = __uint_as_float(to_tf32(wreg[j].w));
            }
        }

        // ---- coalesced epilogue: warp w owns rows [16w, 16w+16) ----
        // lane covers output cols 2*lane, 2*lane+1 -> 256B contiguous per row
        const int chS = (lane >> 2);          // logical chunk of this lane
        #pragma unroll 4
        for (int i = 0; i < 16; i++) {
            int p = 16 * w + i;
            int n = n0 + p;
            if (n >= N) continue;
            int rr  = __ldg(out_index + (size_t)k * N + n);
            int cnt = __ldg(&g_counts[rr]);
            int ch = chS ^ (p & 7);
            float2 v = *reinterpret_cast<const float2*>(
                Ds + p * COUT + ch * 8 + 2 * t);
            float* dst = out + (size_t)rr * COUT + 2 * lane;
            if (cnt == 1) {
                st_cs_v2(dst, v.x + bl.x, v.y + bl.y);
            } else {
                asm volatile("red.global.add.v2.f32 [%0], {%1, %2};"
                             :: "l"(dst), "f"(v.x), "f"(v.y) : "memory");
            }
        }

        __syncthreads();      // Ds free for reuse; W[k+1] visible to all
        buf ^= 1;
    }
}

extern "C" void kernel_launch(void* const* d_in, const int* in_sizes, int n_in,
                              void* d_out, int out_size) {
    const float* feats     = (const float*)d_in[0];   // [N, 64]
    const float* weight    = (const float*)d_in[1];   // [27, 64, 64]
    const float* bias      = (const float*)d_in[2];   // [64]
    const int*   out_index = (const int*)d_in[3];     // [27, N]
    float* out = (float*)d_out;                        // [n_out, 64]

    int N  = in_sizes[0] / CIN;
    int KV = in_sizes[1] / (COUT * CIN);
    int n_out = out_size / COUT;
    int total_idx = in_sizes[3];                       // KV * N

    int z4 = (n_out + 3) / 4;
    zero_counts_kernel<<<(z4 + 255) / 256, 256>>>(z4);
    count_kernel<<<(total_idx + 255) / 256, 256>>>(out_index, total_idx);
    cond_bias_init_kernel<<<(n_out + 255) / 256, 256>>>(
        (const float4*)bias, (float4*)out, n_out);

    const int smem_bytes = SMEM_F * sizeof(float);     // ~100KB
    cudaFuncSetAttribute(spconvt_mma_kernel,
                         cudaFuncAttributeMaxDynamicSharedMemorySize, smem_bytes);
    dim3 grid((N + TILE_N - 1) / TILE_N, (KV + KCHUNK - 1) / KCHUNK);
    spconvt_mma_kernel<<<grid, 256, smem_bytes>>>(feats, weight, bias, out_index,
                                                  out, N, KV);
}

// round 10
// speedup vs baseline: 1.6941x; 1.6941x over previous
#include <cuda_runtime.h>
#include <cstdint>

// Sparse ConvTranspose3d on GB300 (sm_103a) — mma.sync tf32 tensor cores.
//   out[r,:] = bias + sum_{(k,n): out_index[k,n]==r} feats[n,:] @ weight[k,:,:]^T
//
// R10 = R7 (best) with register pressure removed:
//  - feats/weight pre-converted to tf32-rounded copies in __device__ scratch
//  - main kernel fills SMEM via cp.async (no prefetch regs, no cvt in mainloop)
//  - __launch_bounds__(128,3): 3 blocks/SM (12 warps) vs R7's 2 (8 warps)
//  - R7's fragment-order epilogue kept (sector-efficient, ILP-rich)

#define CIN    64
#define COUT   64
#define TILE_N 128
#define KCHUNK 9
#define LDA    68                 // padded row stride (floats), 272B = 16B-multiple
#define MAX_ROWS (60000 * 27)
#define N_PAD  60160               // 470 * 128, >= N rounded to TILE_N

__device__ int   g_counts[MAX_ROWS];
__device__ float g_feats_t[N_PAD * CIN];        // tf32-rounded feats (+zero pad)
__device__ float g_weight_t[27 * COUT * CIN];   // tf32-rounded weights

// ---------------------------------------------------------------- pre-pass ----
__global__ void zero_counts_kernel(int n4) {
    int i = blockIdx.x * blockDim.x + threadIdx.x;
    if (i < n4) reinterpret_cast<int4*>(g_counts)[i] = make_int4(0, 0, 0, 0);
}
__global__ void count_kernel(const int* __restrict__ oi, int total) {
    int i = blockIdx.x * blockDim.x + threadIdx.x;
    if (i < total) atomicAdd(&g_counts[oi[i]], 1);
}
// init rows whose count != 1 (count==0: pure bias; count>=2: bias base for atomics)
__global__ void cond_bias_init_kernel(const float4* __restrict__ bias4,
                                      float4* __restrict__ out4, int n_out) {
    int r = blockIdx.x * blockDim.x + threadIdx.x;
    if (r < n_out && g_counts[r] != 1) {
        #pragma unroll
        for (int j = 0; j < 16; j++) out4[(size_t)r * 16 + j] = bias4[j];
    }
}

__device__ __forceinline__ uint32_t to_tf32(float f) {
    uint32_t u;
    asm("cvt.rna.tf32.f32 %0, %1;" : "=r"(u) : "f"(f));
    return u;
}

// convert feats -> g_feats_t (tf32-rounded), zero-fill padding rows
__global__ void cvt_feats_kernel(const float4* __restrict__ src, int n_f4, int tot_f4) {
    int i = blockIdx.x * blockDim.x + threadIdx.x;
    if (i >= tot_f4) return;
    float4 v = make_float4(0.f, 0.f, 0.f, 0.f);
    if (i < n_f4) v = src[i];
    uint4 o = make_uint4(to_tf32(v.x), to_tf32(v.y), to_tf32(v.z), to_tf32(v.w));
    reinterpret_cast<uint4*>(g_feats_t)[i] = o;
}
__global__ void cvt_weight_kernel(const float4* __restrict__ src, int tot_f4) {
    int i = blockIdx.x * blockDim.x + threadIdx.x;
    if (i >= tot_f4) return;
    float4 v = src[i];
    uint4 o = make_uint4(to_tf32(v.x), to_tf32(v.y), to_tf32(v.z), to_tf32(v.w));
    reinterpret_cast<uint4*>(g_weight_t)[i] = o;
}

// ---------------------------------------------------------------- helpers ----
__device__ __forceinline__ uint32_t f2u(float f) { return __float_as_uint(f); }

__device__ __forceinline__ void mma_tf32(float c[4], const uint32_t a[4],
                                         uint32_t b0, uint32_t b1) {
    asm volatile(
        "mma.sync.aligned.m16n8k8.row.col.f32.tf32.tf32.f32 "
        "{%0,%1,%2,%3}, {%4,%5,%6,%7}, {%8,%9}, {%0,%1,%2,%3};"
        : "+f"(c[0]), "+f"(c[1]), "+f"(c[2]), "+f"(c[3])
        : "r"(a[0]), "r"(a[1]), "r"(a[2]), "r"(a[3]), "r"(b0), "r"(b1));
}

__device__ __forceinline__ void cp16(float* smem_dst, const float* gsrc) {
    unsigned d = (unsigned)__cvta_generic_to_shared(smem_dst);
    asm volatile("cp.async.cg.shared.global [%0], [%1], 16;\n"
                 :: "r"(d), "l"(gsrc));
}

// ------------------------------------------------------------- main kernel ----
__global__ void __launch_bounds__(128, 3) spconvt_mma_kernel(
    const float* __restrict__ bias,      // [64]
    const int*   __restrict__ out_index, // [27, N]
    float*       __restrict__ out,       // [n_out, 64]
    int N, int KV)
{
    extern __shared__ float smem[];
    float* As = smem;                        // 128 x 68
    float* Wb = smem + TILE_N * LDA;         // 2 x (64 x 68)

    const int tid  = threadIdx.x;
    const int w    = tid >> 5;
    const int lane = tid & 31;
    const int g    = lane >> 2;              // group 0..7
    const int t    = lane & 3;               // thread-in-group 0..3
    const int n0   = blockIdx.x * TILE_N;
    const int k0   = blockIdx.y * KCHUNK;

    // ---- A tile via cp.async from pre-converted feats ----
    #pragma unroll
    for (int j = 0; j < 16; j++) {
        int idx = tid + 128 * j;              // 0..2047 float4 slots
        int p = idx >> 4, q = idx & 15;
        cp16(As + p * LDA + q * 4, g_feats_t + (size_t)(n0 + p) * CIN + q * 4);
    }
    // ---- W[k] loader via cp.async ----
    auto cpW = [&](int k, int b) {
        const float* ws = g_weight_t + (size_t)k * COUT * CIN;
        float* dstb = Wb + b * (COUT * LDA);
        #pragma unroll
        for (int j = 0; j < 8; j++) {
            int idx = tid + 128 * j;          // 0..1023
            int c = idx >> 4, q = idx & 15;
            cp16(dstb + c * LDA + q * 4, ws + idx * 4);
        }
        asm volatile("cp.async.commit_group;\n");
    };
    cpW(k0, 0);

    // per-thread bias pairs: bias[8*nt + 2t .. +1]
    float2 b2[8];
    #pragma unroll
    for (int nt = 0; nt < 8; nt++)
        b2[nt] = __ldg(reinterpret_cast<const float2*>(bias) + nt * 4 + t);

    asm volatile("cp.async.wait_group 0;\n" ::: "memory");
    __syncthreads();

    const int p0 = 32 * w + g;                // first of 4 owned point rows
    int buf = 0;

    for (int kk = 0; kk < KCHUNK; kk++) {
        int k = k0 + kk;
        if (k >= KV) break;
        bool more = (kk + 1 < KCHUNK) && (k + 1 < KV);

        // async-prefetch W[k+1] into the other buffer (in flight during MMA)
        if (more) cpW(k + 1, buf ^ 1);

        // prefetch scatter metadata for the 4 owned rows
        int rrv[4], cntv[4];
        #pragma unroll
        for (int j = 0; j < 4; j++) {
            int n = n0 + p0 + 8 * j;
            rrv[j]  = (n < N) ? __ldg(out_index + (size_t)k * N + n) : -1;
            cntv[j] = (rrv[j] >= 0) ? __ldg(&g_counts[rrv[j]]) : 0;
        }

        const float* Wc = Wb + buf * (COUT * LDA);

        float acc[2][8][4];
        #pragma unroll
        for (int mt = 0; mt < 2; mt++)
            #pragma unroll
            for (int nt = 0; nt < 8; nt++)
                #pragma unroll
                for (int x = 0; x < 4; x++) acc[mt][nt][x] = 0.f;

        #pragma unroll
        for (int kc = 0; kc < 8; kc++) {
            const int kb = kc * 8;
            uint32_t a[2][4];
            #pragma unroll
            for (int mt = 0; mt < 2; mt++) {
                int r0 = 32 * w + 16 * mt + g;
                a[mt][0] = f2u(As[(r0)     * LDA + kb + t]);
                a[mt][1] = f2u(As[(r0 + 8) * LDA + kb + t]);
                a[mt][2] = f2u(As[(r0)     * LDA + kb + t + 4]);
                a[mt][3] = f2u(As[(r0 + 8) * LDA + kb + t + 4]);
            }
            #pragma unroll
            for (int nt = 0; nt < 8; nt++) {
                int c = 8 * nt + g;
                uint32_t b0 = f2u(Wc[c * LDA + kb + t]);
                uint32_t b1 = f2u(Wc[c * LDA + kb + t + 4]);
                mma_tf32(acc[0][nt], a[0], b0, b1);
                mma_tf32(acc[1][nt], a[1], b0, b1);
            }
        }

        // ---- scatter epilogue (R7 fragment-order; sector-complete stores) ----
        #pragma unroll
        for (int j = 0; j < 4; j++) {
            if (rrv[j] < 0) continue;
            const int mt = j >> 1, hi = (j & 1) * 2;
            float* dst = out + (size_t)rrv[j] * COUT + 2 * t;
            if (cntv[j] == 1) {
                #pragma unroll
                for (int nt = 0; nt < 8; nt++) {
                    float2 v = make_float2(acc[mt][nt][hi]     + b2[nt].x,
                                           acc[mt][nt][hi + 1] + b2[nt].y);
                    *reinterpret_cast<float2*>(dst + 8 * nt) = v;
                }
            } else {
                #pragma unroll
                for (int nt = 0; nt < 8; nt++) {
                    asm volatile("red.global.add.v2.f32 [%0], {%1, %2};"
                                 :: "l"(dst + 8 * nt),
                                    "f"(acc[mt][nt][hi]), "f"(acc[mt][nt][hi + 1])
                                 : "memory");
                }
            }
        }

        asm volatile("cp.async.wait_group 0;\n" ::: "memory");
        __syncthreads();      // all warps done with buf; W[k+1] visible
        buf ^= 1;
    }
}

extern "C" void kernel_launch(void* const* d_in, const int* in_sizes, int n_in,
                              void* d_out, int out_size) {
    const float* feats     = (const float*)d_in[0];   // [N, 64]
    const float* weight    = (const float*)d_in[1];   // [27, 64, 64]
    const float* bias      = (const float*)d_in[2];   // [64]
    const int*   out_index = (const int*)d_in[3];     // [27, N]
    float* out = (float*)d_out;                        // [n_out, 64]

    int N  = in_sizes[0] / CIN;
    int KV = in_sizes[1] / (COUT * CIN);
    int n_out = out_size / COUT;
    int total_idx = in_sizes[3];                       // KV * N

    int z4 = (n_out + 3) / 4;
    zero_counts_kernel<<<(z4 + 255) / 256, 256>>>(z4);
    count_kernel<<<(total_idx + 255) / 256, 256>>>(out_index, total_idx);
    cond_bias_init_kernel<<<(n_out + 255) / 256, 256>>>(
        (const float4*)bias, (float4*)out, n_out);

    // pre-convert inputs to tf32-rounded scratch
    int n_f4   = in_sizes[0] / 4;                      // N*16
    int tot_f4 = N_PAD * CIN / 4;
    cvt_feats_kernel<<<(tot_f4 + 255) / 256, 256>>>(
        (const float4*)feats, n_f4, tot_f4);
    int w_f4 = in_sizes[1] / 4;
    cvt_weight_kernel<<<(w_f4 + 255) / 256, 256>>>((const float4*)weight, w_f4);

    const int smem_bytes = (TILE_N * LDA + 2 * COUT * LDA) * sizeof(float); // ~68KB
    cudaFuncSetAttribute(spconvt_mma_kernel,
                         cudaFuncAttributeMaxDynamicSharedMemorySize, smem_bytes);
    dim3 grid((N + TILE_N - 1) / TILE_N, (KV + KCHUNK - 1) / KCHUNK);
    spconvt_mma_kernel<<<grid, 128, smem_bytes>>>(bias, out_index, out, N, KV);
}

// round 11
// speedup vs baseline: 1.8233x; 1.0763x over previous
#include <cuda_runtime.h>
#include <cstdint>

// Sparse ConvTranspose3d on GB300 (sm_103a) — mma.sync tf32 tensor cores.
//   out[r,:] = bias + sum_{(k,n): out_index[k,n]==r} feats[n,:] @ weight[k,:,:]^T
//
// R11 = R10 + cout-PERMUTED weights:
//   W rows reordered in the pre-convert pass so that MMA fragment positions of
//   adjacent n8-tiles hold 4 CONSECUTIVE logical output channels. The scatter
//   epilogue then uses STG.128 / red.v4 (16 instrs, 128 L1 wavefronts per
//   warp-k) instead of STG.64 (32 instrs, 256 wavefronts) — attacking the
//   L1tex wavefront floor that bounds rounds 7-10.

#define CIN    64
#define COUT   64
#define TILE_N 128
#define KCHUNK 9
#define LDA    68                 // padded row stride (floats)
#define MAX_ROWS (60000 * 27)
#define N_PAD  60160               // 470 * 128 >= N

__device__ int   g_counts[MAX_ROWS];
__device__ float g_feats_t[N_PAD * CIN];        // tf32-rounded feats (+zero pad)
__device__ float g_weight_t[27 * COUT * CIN];   // tf32-rounded, cout-PERMUTED

// ---------------------------------------------------------------- pre-pass ----
__global__ void zero_counts_kernel(int n4) {
    int i = blockIdx.x * blockDim.x + threadIdx.x;
    if (i < n4) reinterpret_cast<int4*>(g_counts)[i] = make_int4(0, 0, 0, 0);
}
__global__ void count_kernel(const int* __restrict__ oi, int total) {
    int i = blockIdx.x * blockDim.x + threadIdx.x;
    if (i < total) atomicAdd(&g_counts[oi[i]], 1);
}
// init rows whose count != 1 (count==0: pure bias; count>=2: bias base for atomics)
__global__ void cond_bias_init_kernel(const float4* __restrict__ bias4,
                                      float4* __restrict__ out4, int n_out) {
    int r = blockIdx.x * blockDim.x + threadIdx.x;
    if (r < n_out && g_counts[r] != 1) {
        #pragma unroll
        for (int j = 0; j < 16; j++) out4[(size_t)r * 16 + j] = bias4[j];
    }
}

__device__ __forceinline__ uint32_t to_tf32(float f) {
    uint32_t u;
    asm("cvt.rna.tf32.f32 %0, %1;" : "=r"(u) : "f"(f));
    return u;
}

// feats -> g_feats_t (tf32-rounded), zero-fill padding rows
__global__ void cvt_feats_kernel(const float4* __restrict__ src, int n_f4, int tot_f4) {
    int i = blockIdx.x * blockDim.x + threadIdx.x;
    if (i >= tot_f4) return;
    float4 v = make_float4(0.f, 0.f, 0.f, 0.f);
    if (i < n_f4) v = src[i];
    uint4 o = make_uint4(to_tf32(v.x), to_tf32(v.y), to_tf32(v.z), to_tf32(v.w));
    reinterpret_cast<uint4*>(g_feats_t)[i] = o;
}

// weight -> g_weight_t: tf32-rounded AND cout-permuted.
// Fragment position f (0..63) gets logical cout L(f):
//   nt = f>>3, ct = f&7;  L = 16*(nt>>1) + 2*(nt&1) + 4*(ct>>1) + (ct&1)
__global__ void cvt_weight_kernel(const float4* __restrict__ src, int tot_f4) {
    int i = blockIdx.x * blockDim.x + threadIdx.x;
    if (i >= tot_f4) return;                   // tot = 27*64*16
    int q = i & 15;                            // 16B chunk within cin row
    int f = (i >> 4) & 63;                     // fragment row position
    int k = i >> 10;                           // kernel offset
    int nt = f >> 3, ct = f & 7;
    int L = 16 * (nt >> 1) + 2 * (nt & 1) + 4 * (ct >> 1) + (ct & 1);
    float4 v = src[(size_t)k * 1024 + L * 16 + q];
    uint4 o = make_uint4(to_tf32(v.x), to_tf32(v.y), to_tf32(v.z), to_tf32(v.w));
    reinterpret_cast<uint4*>(g_weight_t)[i] = o;
}

// ---------------------------------------------------------------- helpers ----
__device__ __forceinline__ uint32_t f2u(float f) { return __float_as_uint(f); }

__device__ __forceinline__ void mma_tf32(float c[4], const uint32_t a[4],
                                         uint32_t b0, uint32_t b1) {
    asm volatile(
        "mma.sync.aligned.m16n8k8.row.col.f32.tf32.tf32.f32 "
        "{%0,%1,%2,%3}, {%4,%5,%6,%7}, {%8,%9}, {%0,%1,%2,%3};"
        : "+f"(c[0]), "+f"(c[1]), "+f"(c[2]), "+f"(c[3])
        : "r"(a[0]), "r"(a[1]), "r"(a[2]), "r"(a[3]), "r"(b0), "r"(b1));
}

__device__ __forceinline__ void cp16(float* smem_dst, const float* gsrc) {
    unsigned d = (unsigned)__cvta_generic_to_shared(smem_dst);
    asm volatile("cp.async.cg.shared.global [%0], [%1], 16;\n"
                 :: "r"(d), "l"(gsrc));
}

// ------------------------------------------------------------- main kernel ----
__global__ void __launch_bounds__(128, 3) spconvt_mma_kernel(
    const float* __restrict__ bias,      // [64]
    const int*   __restrict__ out_index, // [27, N]
    float*       __restrict__ out,       // [n_out, 64]
    int N, int KV)
{
    extern __shared__ float smem[];
    float* As = smem;                        // 128 x 68
    float* Wb = smem + TILE_N * LDA;         // 2 x (64 x 68)

    const int tid  = threadIdx.x;
    const int w    = tid >> 5;
    const int lane = tid & 31;
    const int g    = lane >> 2;              // group 0..7
    const int t    = lane & 3;               // thread-in-group 0..3
    const int n0   = blockIdx.x * TILE_N;
    const int k0   = blockIdx.y * KCHUNK;

    // ---- A tile via cp.async from pre-converted feats ----
    #pragma unroll
    for (int j = 0; j < 16; j++) {
        int idx = tid + 128 * j;              // 0..2047 float4 slots
        int p = idx >> 4, q = idx & 15;
        cp16(As + p * LDA + q * 4, g_feats_t + (size_t)(n0 + p) * CIN + q * 4);
    }
    // ---- W[k] loader via cp.async (permuted source) ----
    auto cpW = [&](int k, int b) {
        const float* ws = g_weight_t + (size_t)k * COUT * CIN;
        float* dstb = Wb + b * (COUT * LDA);
        #pragma unroll
        for (int j = 0; j < 8; j++) {
            int idx = tid + 128 * j;          // 0..1023
            int c = idx >> 4, q = idx & 15;
            cp16(dstb + c * LDA + q * 4, ws + idx * 4);
        }
        asm volatile("cp.async.commit_group;\n");
    };
    cpW(k0, 0);

    // per-thread bias float4s: logical couts [16m + 4t, +4) -> bias4[4m + t]
    float4 b4[4];
    #pragma unroll
    for (int m = 0; m < 4; m++)
        b4[m] = __ldg(reinterpret_cast<const float4*>(bias) + 4 * m + t);

    asm volatile("cp.async.wait_group 0;\n" ::: "memory");
    __syncthreads();

    const int p0 = 32 * w + g;                // first of 4 owned point rows
    int buf = 0;

    for (int kk = 0; kk < KCHUNK; kk++) {
        int k = k0 + kk;
        if (k >= KV) break;
        bool more = (kk + 1 < KCHUNK) && (k + 1 < KV);

        // async-prefetch W[k+1] into the other buffer
        if (more) cpW(k + 1, buf ^ 1);

        // prefetch scatter metadata for the 4 owned rows
        int rrv[4], cntv[4];
        #pragma unroll
        for (int j = 0; j < 4; j++) {
            int n = n0 + p0 + 8 * j;
            rrv[j]  = (n < N) ? __ldg(out_index + (size_t)k * N + n) : -1;
            cntv[j] = (rrv[j] >= 0) ? __ldg(&g_counts[rrv[j]]) : 0;
        }

        const float* Wc = Wb + buf * (COUT * LDA);

        float acc[2][8][4];
        #pragma unroll
        for (int mt = 0; mt < 2; mt++)
            #pragma unroll
            for (int nt = 0; nt < 8; nt++)
                #pragma unroll
                for (int x = 0; x < 4; x++) acc[mt][nt][x] = 0.f;

        #pragma unroll
        for (int kc = 0; kc < 8; kc++) {
            const int kb = kc * 8;
            uint32_t a[2][4];
            #pragma unroll
            for (int mt = 0; mt < 2; mt++) {
                int r0 = 32 * w + 16 * mt + g;
                a[mt][0] = f2u(As[(r0)     * LDA + kb + t]);
                a[mt][1] = f2u(As[(r0 + 8) * LDA + kb + t]);
                a[mt][2] = f2u(As[(r0)     * LDA + kb + t + 4]);
                a[mt][3] = f2u(As[(r0 + 8) * LDA + kb + t + 4]);
            }
            #pragma unroll
            for (int nt = 0; nt < 8; nt++) {
                int c = 8 * nt + g;
                uint32_t b0 = f2u(Wc[c * LDA + kb + t]);
                uint32_t b1 = f2u(Wc[c * LDA + kb + t + 4]);
                mma_tf32(acc[0][nt], a[0], b0, b1);
                mma_tf32(acc[1][nt], a[1], b0, b1);
            }
        }

        // ---- scatter epilogue: v4 stores on permuted-contiguous couts ----
        // lane (g,t) holds logical couts [16m+4t, 16m+4t+4) in
        // {acc[mt][2m][hi], acc[mt][2m][hi+1], acc[mt][2m+1][hi], acc[mt][2m+1][hi+1]}
        #pragma unroll
        for (int j = 0; j < 4; j++) {
            if (rrv[j] < 0) continue;
            const int mt = j >> 1, hi = (j & 1) * 2;
            float* dst = out + (size_t)rrv[j] * COUT + 4 * t;
            if (cntv[j] == 1) {
                #pragma unroll
                for (int m = 0; m < 4; m++) {
                    float4 v = make_float4(acc[mt][2*m][hi]       + b4[m].x,
                                           acc[mt][2*m][hi + 1]   + b4[m].y,
                                           acc[mt][2*m+1][hi]     + b4[m].z,
                                           acc[mt][2*m+1][hi + 1] + b4[m].w);
                    *reinterpret_cast<float4*>(dst + 16 * m) = v;
                }
            } else {
                #pragma unroll
                for (int m = 0; m < 4; m++) {
                    asm volatile("red.global.add.v4.f32 [%0], {%1, %2, %3, %4};"
                                 :: "l"(dst + 16 * m),
                                    "f"(acc[mt][2*m][hi]),
                                    "f"(acc[mt][2*m][hi + 1]),
                                    "f"(acc[mt][2*m+1][hi]),
                                    "f"(acc[mt][2*m+1][hi + 1])
                                 : "memory");
                }
            }
        }

        asm volatile("cp.async.wait_group 0;\n" ::: "memory");
        __syncthreads();      // all warps done with buf; W[k+1] visible
        buf ^= 1;
    }
}

extern "C" void kernel_launch(void* const* d_in, const int* in_sizes, int n_in,
                              void* d_out, int out_size) {
    const float* feats     = (const float*)d_in[0];   // [N, 64]
    const float* weight    = (const float*)d_in[1];   // [27, 64, 64]
    const float* bias      = (const float*)d_in[2];   // [64]
    const int*   out_index = (const int*)d_in[3];     // [27, N]
    float* out = (float*)d_out;                        // [n_out, 64]

    int N  = in_sizes[0] / CIN;
    int KV = in_sizes[1] / (COUT * CIN);
    int n_out = out_size / COUT;
    int total_idx = in_sizes[3];                       // KV * N

    int z4 = (n_out + 3) / 4;
    zero_counts_kernel<<<(z4 + 255) / 256, 256>>>(z4);
    count_kernel<<<(total_idx + 255) / 256, 256>>>(out_index, total_idx);
    cond_bias_init_kernel<<<(n_out + 255) / 256, 256>>>(
        (const float4*)bias, (float4*)out, n_out);

    // pre-convert inputs (feats: tf32-round; weight: tf32-round + cout-permute)
    int n_f4   = in_sizes[0] / 4;
    int tot_f4 = N_PAD * CIN / 4;
    cvt_feats_kernel<<<(tot_f4 + 255) / 256, 256>>>(
        (const float4*)feats, n_f4, tot_f4);
    int w_f4 = in_sizes[1] / 4;
    cvt_weight_kernel<<<(w_f4 + 255) / 256, 256>>>((const float4*)weight, w_f4);

    const int smem_bytes = (TILE_N * LDA + 2 * COUT * LDA) * sizeof(float); // ~68KB
    cudaFuncSetAttribute(spconvt_mma_kernel,
                         cudaFuncAttributeMaxDynamicSharedMemorySize, smem_bytes);
    dim3 grid((N + TILE_N - 1) / TILE_N, (KV + KCHUNK - 1) / KCHUNK);
    spconvt_mma_kernel<<<grid, 128, smem_bytes>>>(bias, out_index, out, N, KV);
}

// round 12
// speedup vs baseline: 1.9015x; 1.0429x over previous
#include <cuda_runtime.h>
#include <cstdint>

// Sparse ConvTranspose3d on GB300 (sm_103a) — mma.sync tf32 tensor cores.
//   out[r,:] = bias + sum_{(k,n): out_index[k,n]==r} feats[n,:] @ weight[k,:,:]^T
//
// R12 = R11 + FRAGMENT-MAJOR PREPACKING:
//   feats and weight are pre-gathered into MMA-fragment order, so the mainloop
//   feeds each m16n8k8 MMA with LDS.128 loads only:
//     A: 1 LDS.128 per (kc, mt)   [was 4 LDS.32]
//     B: 4 LDS.128 per kc (b-pairs for all 8 nt)  [was 16 LDS.32]
//   Per-warp-k LDS wavefronts: 192 -> 48. SMEM flat 64KB, conflict-free by
//   construction. Cout permutation (R11) baked into the weight prepack, so the
//   v4 scatter epilogue is unchanged.

#define CIN    64
#define COUT   64
#define TILE_N 128
#define KCHUNK 9
#define MAX_ROWS (60000 * 27)
#define N_PAD  60160                       // 470 * 128 >= N
#define NTILES (N_PAD / TILE_N)            // 470

__device__ int   g_counts[MAX_ROWS];
__device__ float g_feats_f[N_PAD * CIN];        // fragment-major feats (tf32)
__device__ float g_weight_f[27 * COUT * CIN];   // fragment-major, cout-permuted

// ---------------------------------------------------------------- pre-pass ----
__global__ void zero_counts_kernel(int n4) {
    int i = blockIdx.x * blockDim.x + threadIdx.x;
    if (i < n4) reinterpret_cast<int4*>(g_counts)[i] = make_int4(0, 0, 0, 0);
}
__global__ void count_kernel(const int* __restrict__ oi, int total) {
    int i = blockIdx.x * blockDim.x + threadIdx.x;
    if (i < total) atomicAdd(&g_counts[oi[i]], 1);
}
__global__ void cond_bias_init_kernel(const float4* __restrict__ bias4,
                                      float4* __restrict__ out4, int n_out) {
    int r = blockIdx.x * blockDim.x + threadIdx.x;
    if (r < n_out && g_counts[r] != 1) {
        #pragma unroll
        for (int j = 0; j < 16; j++) out4[(size_t)r * 16 + j] = bias4[j];
    }
}

__device__ __forceinline__ uint32_t to_tf32(float f) {
    uint32_t u;
    asm("cvt.rna.tf32.f32 %0, %1;" : "=r"(u) : "f"(f));
    return u;
}

// feats -> fragment-major: slot i = (tile, mi, kc, lane); 4 floats each.
//   lane=(g,t): v = { A[16mi+g][8kc+t], A[16mi+8+g][8kc+t],
//                     A[16mi+g][8kc+t+4], A[16mi+8+g][8kc+t+4] }  (rows rel. tile)
__global__ void prep_feats_kernel(const float* __restrict__ feats, int N, int tot) {
    int i = blockIdx.x * blockDim.x + threadIdx.x;
    if (i >= tot) return;                       // tot = NTILES*2048
    int lane = i & 31;
    int kc   = (i >> 5) & 7;
    int mi   = (i >> 8) & 7;
    int tile = i >> 11;
    int g = lane >> 2, t = lane & 3;
    int r0 = tile * TILE_N + mi * 16 + g;
    int r1 = r0 + 8;
    int c0 = kc * 8 + t;
    float v0 = (r0 < N) ? feats[(size_t)r0 * CIN + c0]     : 0.f;
    float v1 = (r1 < N) ? feats[(size_t)r1 * CIN + c0]     : 0.f;
    float v2 = (r0 < N) ? feats[(size_t)r0 * CIN + c0 + 4] : 0.f;
    float v3 = (r1 < N) ? feats[(size_t)r1 * CIN + c0 + 4] : 0.f;
    uint4 o = make_uint4(to_tf32(v0), to_tf32(v1), to_tf32(v2), to_tf32(v3));
    reinterpret_cast<uint4*>(g_feats_f)[i] = o;
}

// weight -> fragment-major with cout permutation L(f):
//   slot i = (k, kc, m, lane); v = { Wp[16m+g][8kc+t], Wp[16m+g][8kc+t+4],
//                                    Wp[16m+8+g][8kc+t], Wp[16m+8+g][8kc+t+4] }
//   where Wp[f][:] = W[L(f)][:],  L(f)=16*(nt>>1)+2*(nt&1)+4*(ct>>1)+(ct&1),
//   nt=f>>3, ct=f&7.
__device__ __forceinline__ int Lperm(int f) {
    int nt = f >> 3, ct = f & 7;
    return 16 * (nt >> 1) + 2 * (nt & 1) + 4 * (ct >> 1) + (ct & 1);
}
__global__ void prep_weight_kernel(const float* __restrict__ w, int tot) {
    int i = blockIdx.x * blockDim.x + threadIdx.x;
    if (i >= tot) return;                       // tot = 27*1024
    int lane = i & 31;
    int m    = (i >> 5) & 3;
    int kc   = (i >> 7) & 7;
    int k    = i >> 10;
    int g = lane >> 2, t = lane & 3;
    int f0 = 8 * (2 * m)     + g;               // nt = 2m
    int f1 = 8 * (2 * m + 1) + g;               // nt = 2m+1
    const float* wk = w + (size_t)k * COUT * CIN;
    int c0 = kc * 8 + t;
    float v0 = wk[Lperm(f0) * CIN + c0];
    float v1 = wk[Lperm(f0) * CIN + c0 + 4];
    float v2 = wk[Lperm(f1) * CIN + c0];
    float v3 = wk[Lperm(f1) * CIN + c0 + 4];
    uint4 o = make_uint4(to_tf32(v0), to_tf32(v1), to_tf32(v2), to_tf32(v3));
    reinterpret_cast<uint4*>(g_weight_f)[i] = o;
}

// ---------------------------------------------------------------- helpers ----
__device__ __forceinline__ uint32_t f2u(float f) { return __float_as_uint(f); }

__device__ __forceinline__ void mma_tf32(float c[4], const uint32_t a[4],
                                         uint32_t b0, uint32_t b1) {
    asm volatile(
        "mma.sync.aligned.m16n8k8.row.col.f32.tf32.tf32.f32 "
        "{%0,%1,%2,%3}, {%4,%5,%6,%7}, {%8,%9}, {%0,%1,%2,%3};"
        : "+f"(c[0]), "+f"(c[1]), "+f"(c[2]), "+f"(c[3])
        : "r"(a[0]), "r"(a[1]), "r"(a[2]), "r"(a[3]), "r"(b0), "r"(b1));
}

__device__ __forceinline__ void cp16(float* smem_dst, const float* gsrc) {
    unsigned d = (unsigned)__cvta_generic_to_shared(smem_dst);
    asm volatile("cp.async.cg.shared.global [%0], [%1], 16;\n"
                 :: "r"(d), "l"(gsrc));
}

// ------------------------------------------------------------- main kernel ----
// dyn smem (floats): As[8192] (32KB) | Wb[2 x 4096] (2 x 16KB)  = 64KB flat
#define A_FLOATS 8192
#define W_FLOATS 4096

__global__ void __launch_bounds__(128, 3) spconvt_mma_kernel(
    const float* __restrict__ bias,      // [64]
    const int*   __restrict__ out_index, // [27, N]
    float*       __restrict__ out,       // [n_out, 64]
    int N, int KV)
{
    extern __shared__ float smem[];
    float* As = smem;                        // fragment-major A tile
    float* Wb = smem + A_FLOATS;             // 2 fragment-major W buffers

    const int tid  = threadIdx.x;
    const int w    = tid >> 5;
    const int lane = tid & 31;
    const int g    = lane >> 2;
    const int t    = lane & 3;
    const int n0   = blockIdx.x * TILE_N;
    const int k0   = blockIdx.y * KCHUNK;

    // ---- A tile: straight 32KB async copy (already fragment-major) ----
    {
        const float* src = g_feats_f + (size_t)blockIdx.x * A_FLOATS;
        #pragma unroll
        for (int j = 0; j < 16; j++) {
            int idx = tid + 128 * j;          // 0..2047 float4 slots
            cp16(As + idx * 4, src + idx * 4);
        }
    }
    // ---- W[k] loader: straight 16KB async copy ----
    auto cpW = [&](int k, int b) {
        const float* src = g_weight_f + (size_t)k * W_FLOATS;
        float* dst = Wb + b * W_FLOATS;
        #pragma unroll
        for (int j = 0; j < 8; j++) {
            int idx = tid + 128 * j;          // 0..1023
            cp16(dst + idx * 4, src + idx * 4);
        }
        asm volatile("cp.async.commit_group;\n");
    };
    cpW(k0, 0);

    // per-thread bias float4s: logical couts [16m+4t, +4) -> bias4[4m + t]
    float4 b4[4];
    #pragma unroll
    for (int m = 0; m < 4; m++)
        b4[m] = __ldg(reinterpret_cast<const float4*>(bias) + 4 * m + t);

    asm volatile("cp.async.wait_group 0;\n" ::: "memory");
    __syncthreads();

    const int p0 = 32 * w + g;                // first of 4 owned point rows
    int buf = 0;

    for (int kk = 0; kk < KCHUNK; kk++) {
        int k = k0 + kk;
        if (k >= KV) break;
        bool more = (kk + 1 < KCHUNK) && (k + 1 < KV);

        if (more) cpW(k + 1, buf ^ 1);

        // prefetch scatter metadata
        int rrv[4], cntv[4];
        #pragma unroll
        for (int j = 0; j < 4; j++) {
            int n = n0 + p0 + 8 * j;
            rrv[j]  = (n < N) ? __ldg(out_index + (size_t)k * N + n) : -1;
            cntv[j] = (rrv[j] >= 0) ? __ldg(&g_counts[rrv[j]]) : 0;
        }

        const float* Wc = Wb + buf * W_FLOATS;

        float acc[2][8][4];
        #pragma unroll
        for (int mt = 0; mt < 2; mt++)
            #pragma unroll
            for (int nt = 0; nt < 8; nt++)
                #pragma unroll
                for (int x = 0; x < 4; x++) acc[mt][nt][x] = 0.f;

        #pragma unroll
        for (int kc = 0; kc < 8; kc++) {
            // A fragments: 1 LDS.128 per mt   (mi = 2w + mt)
            uint32_t a[2][4];
            #pragma unroll
            for (int mt = 0; mt < 2; mt++) {
                float4 av = *reinterpret_cast<const float4*>(
                    As + (((2 * w + mt) * 8 + kc) * 32 + lane) * 4);
                a[mt][0] = f2u(av.x); a[mt][1] = f2u(av.y);
                a[mt][2] = f2u(av.z); a[mt][3] = f2u(av.w);
            }
            // B fragments: 4 LDS.128 -> b-pairs for all 8 nt
            #pragma unroll
            for (int m = 0; m < 4; m++) {
                float4 bv = *reinterpret_cast<const float4*>(
                    Wc + ((kc * 4 + m) * 32 + lane) * 4);
                uint32_t b0a = f2u(bv.x), b1a = f2u(bv.y);   // nt = 2m
                uint32_t b0b = f2u(bv.z), b1b = f2u(bv.w);   // nt = 2m+1
                mma_tf32(acc[0][2 * m],     a[0], b0a, b1a);
                mma_tf32(acc[1][2 * m],     a[1], b0a, b1a);
                mma_tf32(acc[0][2 * m + 1], a[0], b0b, b1b);
                mma_tf32(acc[1][2 * m + 1], a[1], b0b, b1b);
            }
        }

        // ---- scatter epilogue (R11 v4 form, permutation identical) ----
        #pragma unroll
        for (int j = 0; j < 4; j++) {
            if (rrv[j] < 0) continue;
            const int mt = j >> 1, hi = (j & 1) * 2;
            float* dst = out + (size_t)rrv[j] * COUT + 4 * t;
            if (cntv[j] == 1) {
                #pragma unroll
                for (int m = 0; m < 4; m++) {
                    float4 v = make_float4(acc[mt][2*m][hi]       + b4[m].x,
                                           acc[mt][2*m][hi + 1]   + b4[m].y,
                                           acc[mt][2*m+1][hi]     + b4[m].z,
                                           acc[mt][2*m+1][hi + 1] + b4[m].w);
                    *reinterpret_cast<float4*>(dst + 16 * m) = v;
                }
            } else {
                #pragma unroll
                for (int m = 0; m < 4; m++) {
                    asm volatile("red.global.add.v4.f32 [%0], {%1, %2, %3, %4};"
                                 :: "l"(dst + 16 * m),
                                    "f"(acc[mt][2*m][hi]),
                                    "f"(acc[mt][2*m][hi + 1]),
                                    "f"(acc[mt][2*m+1][hi]),
                                    "f"(acc[mt][2*m+1][hi + 1])
                                 : "memory");
                }
            }
        }

        asm volatile("cp.async.wait_group 0;\n" ::: "memory");
        __syncthreads();
        buf ^= 1;
    }
}

extern "C" void kernel_launch(void* const* d_in, const int* in_sizes, int n_in,
                              void* d_out, int out_size) {
    const float* feats     = (const float*)d_in[0];   // [N, 64]
    const float* weight    = (const float*)d_in[1];   // [27, 64, 64]
    const float* bias      = (const float*)d_in[2];   // [64]
    const int*   out_index = (const int*)d_in[3];     // [27, N]
    float* out = (float*)d_out;                        // [n_out, 64]

    int N  = in_sizes[0] / CIN;
    int KV = in_sizes[1] / (COUT * CIN);
    int n_out = out_size / COUT;
    int total_idx = in_sizes[3];                       // KV * N

    int z4 = (n_out + 3) / 4;
    zero_counts_kernel<<<(z4 + 255) / 256, 256>>>(z4);
    count_kernel<<<(total_idx + 255) / 256, 256>>>(out_index, total_idx);
    cond_bias_init_kernel<<<(n_out + 255) / 256, 256>>>(
        (const float4*)bias, (float4*)out, n_out);

    // fragment-major prepack
    int tot_a = NTILES * 2048;
    prep_feats_kernel<<<(tot_a + 255) / 256, 256>>>(feats, N, tot_a);
    int tot_w = KV * 1024;
    prep_weight_kernel<<<(tot_w + 255) / 256, 256>>>(weight, tot_w);

    const int smem_bytes = (A_FLOATS + 2 * W_FLOATS) * sizeof(float);  // 64KB
    cudaFuncSetAttribute(spconvt_mma_kernel,
                         cudaFuncAttributeMaxDynamicSharedMemorySize, smem_bytes);
    dim3 grid((N + TILE_N - 1) / TILE_N, (KV + KCHUNK - 1) / KCHUNK);
    spconvt_mma_kernel<<<grid, 128, smem_bytes>>>(bias, out_index, out, N, KV);
}